// round 1
// baseline (speedup 1.0000x reference)
#include <cuda_runtime.h>
#include <math.h>

#define B_   4
#define N_   40000
#define E_   240000
#define K_   128
#define CW_  128
#define ROWS_TOT (B_*N_)          // 160000
#define NC   (B_*N_*CW_)          // 20,480,000 floats per buffer

// ---- scratch (static __device__, allocation-free per harness rules) ----
__device__ float g_x  [NC];
__device__ float g_xd [NC];
__device__ float g_gX [NC];
__device__ float g_gY [NC];
__device__ float g_bre[NC];
__device__ float g_bim[NC];
__device__ float g_gf [NC];
__device__ float g_h1 [NC];
__device__ float g_h2 [NC];
__device__ float g_spec[B_*K_*CW_];

enum { EPI_NONE = 0, EPI_BIAS = 1, EPI_BRELU = 2, EPI_BRES = 3 };

// ---------------------------------------------------------------------------
// zero: vectorized float4 clear
// ---------------------------------------------------------------------------
__global__ void zero_k(float4* __restrict__ p, int n4) {
    int i = blockIdx.x * blockDim.x + threadIdx.x;
    if (i < n4) p[i] = make_float4(0.f, 0.f, 0.f, 0.f);
}

// ---------------------------------------------------------------------------
// first: x = x_in @ w_first + b_first   ([160000,6] @ [6,128])
// ---------------------------------------------------------------------------
__global__ __launch_bounds__(128) void first_k(
    const float* __restrict__ x_in, const float* __restrict__ w,
    const float* __restrict__ bias, float* __restrict__ x)
{
    __shared__ float sW[6 * 128];
    __shared__ float sB[128];
    __shared__ float sX[32 * 6];
    int tid = threadIdx.x;
    long m0 = (long)blockIdx.x * 32;
    for (int idx = tid; idx < 768; idx += 128) sW[idx] = __ldg(w + idx);
    sB[tid] = __ldg(bias + tid);
    for (int idx = tid; idx < 192; idx += 128) sX[idx] = __ldg(x_in + m0 * 6 + idx);
    __syncthreads();
    #pragma unroll 4
    for (int r = 0; r < 32; r++) {
        float a = sB[tid];
        #pragma unroll
        for (int t = 0; t < 6; t++) a += sX[r * 6 + t] * sW[t * 128 + tid];
        x[(m0 + r) * 128 + tid] = a;
    }
}

// ---------------------------------------------------------------------------
// last: out = x @ w_last + b_last   ([160000,128] @ [128,3])
// ---------------------------------------------------------------------------
__global__ __launch_bounds__(128) void last_k(
    const float* __restrict__ x, const float* __restrict__ w,
    const float* __restrict__ bias, float* __restrict__ out)
{
    __shared__ float sX[32 * 128];
    __shared__ float sW[128 * 3];
    __shared__ float sB[3];
    int tid = threadIdx.x;
    long m0 = (long)blockIdx.x * 32;
    for (int idx = tid; idx < 384; idx += 128) sW[idx] = __ldg(w + idx);
    if (tid < 3) sB[tid] = __ldg(bias + tid);
    for (int idx = tid; idx < 1024; idx += 128)
        ((float4*)sX)[idx] = __ldg((const float4*)(x + m0 * 128) + idx);
    __syncthreads();
    if (tid < 96) {
        int r = tid / 3, c = tid % 3;
        float a = sB[c];
        #pragma unroll 8
        for (int k = 0; k < 128; k++) a += sX[r * 128 + k] * sW[k * 3 + c];
        out[(m0 + r) * 3 + c] = a;
    }
}

// ---------------------------------------------------------------------------
// spectral forward: spec[b,k,c] += sum_n evecs[b,n,k] * mass[b,n] * x[b,n,c]
// block: 256 threads, 8x8 microtile per thread covering full 128x128 output;
// chunk of N rows per block, atomic finish into g_spec.
// ---------------------------------------------------------------------------
#define SF_TS 16
__global__ __launch_bounds__(256) void spec_fwd_k(
    const float* __restrict__ evecs, const float* __restrict__ x,
    const float* __restrict__ mass, float* __restrict__ spec, int chunk)
{
    __shared__ float sE[SF_TS][128];
    __shared__ float sX[SF_TS][128];
    int b  = blockIdx.y;
    int n0 = blockIdx.x * chunk;
    int n1 = min(n0 + chunk, N_);
    int tid = threadIdx.x;
    int cg = tid & 15, kg = tid >> 4;
    int k0 = kg * 8, c0 = cg * 8;
    float acc[8][8];
    #pragma unroll
    for (int i = 0; i < 8; i++)
        #pragma unroll
        for (int j = 0; j < 8; j++) acc[i][j] = 0.f;

    const float* Eb = evecs + (long)b * N_ * 128;
    const float* Xb = x     + (long)b * N_ * 128;
    const float* Mb = mass  + (long)b * N_;

    for (int nt = n0; nt < n1; nt += SF_TS) {
        for (int idx = tid; idx < SF_TS * 32; idx += 256) {
            int r = idx >> 5, q = idx & 31;
            int n = nt + r;
            float4 e4 = make_float4(0.f, 0.f, 0.f, 0.f);
            float4 x4 = make_float4(0.f, 0.f, 0.f, 0.f);
            if (n < n1) {
                e4 = __ldg((const float4*)(Eb + (long)n * 128) + q);
                float m = __ldg(Mb + n);
                x4 = __ldg((const float4*)(Xb + (long)n * 128) + q);
                x4.x *= m; x4.y *= m; x4.z *= m; x4.w *= m;
            }
            ((float4*)sE[r])[q] = e4;
            ((float4*)sX[r])[q] = x4;
        }
        __syncthreads();
        #pragma unroll 4
        for (int t = 0; t < SF_TS; t++) {
            float4 ea = *(const float4*)&sE[t][k0];
            float4 eb = *(const float4*)&sE[t][k0 + 4];
            float4 xa = *(const float4*)&sX[t][c0];
            float4 xb = *(const float4*)&sX[t][c0 + 4];
            float e[8] = {ea.x, ea.y, ea.z, ea.w, eb.x, eb.y, eb.z, eb.w};
            float v[8] = {xa.x, xa.y, xa.z, xa.w, xb.x, xb.y, xb.z, xb.w};
            #pragma unroll
            for (int i = 0; i < 8; i++)
                #pragma unroll
                for (int j = 0; j < 8; j++) acc[i][j] += e[i] * v[j];
        }
        __syncthreads();
    }
    float* Sb = spec + (long)b * K_ * CW_;
    #pragma unroll
    for (int i = 0; i < 8; i++)
        #pragma unroll
        for (int j = 0; j < 8; j++)
            atomicAdd(Sb + (long)(k0 + i) * 128 + (c0 + j), acc[i][j]);
}

// ---------------------------------------------------------------------------
// spec scale: spec[b,k,c] *= exp(-evals[b,k] * dt[c])
// ---------------------------------------------------------------------------
__global__ void spec_scale_k(float* __restrict__ spec,
                             const float* __restrict__ evals,
                             const float* __restrict__ dt)
{
    int idx = blockIdx.x * 256 + threadIdx.x;      // 65536 total
    int b = idx >> 14, k = (idx >> 7) & 127, c = idx & 127;
    spec[idx] *= __expf(-__ldg(evals + b * K_ + k) * __ldg(dt + c));
}

// ---------------------------------------------------------------------------
// generic fp32 GEMM: C[m,c] = epi( sum_j s_j * A_j[m,:] @ W_j[:,c] )
// K fixed = 128 per input. TM=64 rows/block, 256 threads, 8x4 microtile.
// grid.y = batch (A/C advance M*128, W advances wstride).
// dynamic smem: sW 64KB + sA 32KB
// ---------------------------------------------------------------------------
__global__ __launch_bounds__(256) void gemm_k(
    const float* __restrict__ A0, const float* __restrict__ W0, float s0,
    const float* __restrict__ A1, const float* __restrict__ W1, float s1,
    const float* __restrict__ A2, const float* __restrict__ W2, float s2,
    const float* __restrict__ bias, const float* __restrict__ resid,
    float* __restrict__ C, int M, int num_in, int epi, int wstride)
{
    extern __shared__ float smem[];
    float* sW = smem;            // 128*128
    float* sA = smem + 16384;    // 64*128

    int tid = threadIdx.x;
    int zb  = blockIdx.y;
    long aoff = (long)zb * M * 128;
    long woff = (long)zb * wstride;
    int m0 = blockIdx.x * 64;
    int cg = tid & 31, rg = tid >> 5;
    int c0 = cg * 4, r0 = rg * 8;

    float acc[8][4];
    #pragma unroll
    for (int i = 0; i < 8; i++)
        #pragma unroll
        for (int j = 0; j < 4; j++) acc[i][j] = 0.f;

    const float* As[3] = {A0, A1, A2};
    const float* Ws[3] = {W0, W1, W2};
    float ss[3] = {s0, s1, s2};

    for (int jin = 0; jin < num_in; jin++) {
        const float* A = As[jin] + aoff;
        const float* W = Ws[jin] + woff;
        float s = ss[jin];
        for (int idx = tid; idx < 4096; idx += 256) {
            float4 w = __ldg((const float4*)W + idx);
            w.x *= s; w.y *= s; w.z *= s; w.w *= s;
            ((float4*)sW)[idx] = w;
        }
        for (int idx = tid; idx < 2048; idx += 256) {
            int r = idx >> 5;
            ((float4*)sA)[idx] =
                __ldg((const float4*)(A + (long)(m0 + r) * 128) + (idx & 31));
        }
        __syncthreads();
        #pragma unroll 4
        for (int k = 0; k < 128; k++) {
            float4 w4 = ((const float4*)(sW + k * 128))[cg];
            float a[8];
            #pragma unroll
            for (int i = 0; i < 8; i++) a[i] = sA[(r0 + i) * 128 + k];
            #pragma unroll
            for (int i = 0; i < 8; i++) {
                acc[i][0] += a[i] * w4.x;
                acc[i][1] += a[i] * w4.y;
                acc[i][2] += a[i] * w4.z;
                acc[i][3] += a[i] * w4.w;
            }
        }
        __syncthreads();
    }

    float4 b4 = make_float4(0.f, 0.f, 0.f, 0.f);
    if (epi != EPI_NONE) b4 = __ldg((const float4*)bias + cg);
    #pragma unroll
    for (int i = 0; i < 8; i++) {
        long row = (long)(m0 + r0 + i);
        float4 o = make_float4(acc[i][0] + b4.x, acc[i][1] + b4.y,
                               acc[i][2] + b4.z, acc[i][3] + b4.w);
        if (epi == EPI_BRELU) {
            o.x = fmaxf(o.x, 0.f); o.y = fmaxf(o.y, 0.f);
            o.z = fmaxf(o.z, 0.f); o.w = fmaxf(o.w, 0.f);
        } else if (epi == EPI_BRES) {
            float4 rv = __ldg((const float4*)(resid + aoff + row * 128) + cg);
            o.x += rv.x; o.y += rv.y; o.z += rv.z; o.w += rv.w;
        }
        *(float4*)(C + aoff + row * 128 + c0) = o;
    }
}

// ---------------------------------------------------------------------------
// SPMM (both operators at once): for each edge e (per batch b):
//   gX[b, rows[e], :] += gradX[b,e] * xd[b, cols[e], :]   (same for gY)
// 128 threads = channels, 8 edges per block.
// ---------------------------------------------------------------------------
#define SP_EPB 8
__global__ __launch_bounds__(128) void spmm_k(
    const int* __restrict__ rows, const int* __restrict__ cols,
    const float* __restrict__ gxv, const float* __restrict__ gyv,
    const float* __restrict__ xd, float* __restrict__ gX, float* __restrict__ gY)
{
    int b = blockIdx.y;
    int c = threadIdx.x;
    int e0 = blockIdx.x * SP_EPB;
    const float* xb = xd + (long)b * N_ * 128;
    float* gxb = gX + (long)b * N_ * 128;
    float* gyb = gY + (long)b * N_ * 128;
    #pragma unroll
    for (int q = 0; q < SP_EPB; q++) {
        int e = e0 + q;
        int r   = __ldg(rows + e);
        int col = __ldg(cols + e);
        float vx = __ldg(gxv + (long)b * E_ + e);
        float vy = __ldg(gyv + (long)b * E_ + e);
        float xv = __ldg(xb + (long)col * 128 + c);
        atomicAdd(gxb + (long)r * 128 + c, vx * xv);
        atomicAdd(gyb + (long)r * 128 + c, vy * xv);
    }
}

// ---------------------------------------------------------------------------
// grad feature: gf = tanh(gX * Breal + gY * Bimag)
// ---------------------------------------------------------------------------
__global__ void gradfeat_k(const float4* __restrict__ gX, const float4* __restrict__ gY,
                           const float4* __restrict__ br, const float4* __restrict__ bi,
                           float4* __restrict__ gf, int n4)
{
    int i = blockIdx.x * blockDim.x + threadIdx.x;
    if (i >= n4) return;
    float4 a = gX[i], b = gY[i], r = br[i], m = bi[i];
    float4 o;
    o.x = tanhf(a.x * r.x + b.x * m.x);
    o.y = tanhf(a.y * r.y + b.y * m.y);
    o.z = tanhf(a.z * r.z + b.z * m.z);
    o.w = tanhf(a.w * r.w + b.w * m.w);
    gf[i] = o;
}

// ---------------------------------------------------------------------------
extern "C" void kernel_launch(void* const* d_in, const int* in_sizes, int n_in,
                              void* d_out, int out_size)
{
    const float* x_in    = (const float*)d_in[0];
    const float* mass    = (const float*)d_in[1];
    const float* evals   = (const float*)d_in[2];
    const float* evecs   = (const float*)d_in[3];
    const int*   rows    = (const int*)  d_in[4];
    const int*   cols    = (const int*)  d_in[5];
    const float* gradX   = (const float*)d_in[6];
    const float* gradY   = (const float*)d_in[7];
    const float* w_first = (const float*)d_in[8];
    const float* b_first = (const float*)d_in[9];
    const float* dtim    = (const float*)d_in[10];
    const float* A_re    = (const float*)d_in[11];
    const float* A_im    = (const float*)d_in[12];
    const float* mlp_w0  = (const float*)d_in[13];
    const float* mlp_b0  = (const float*)d_in[14];
    const float* mlp_w1  = (const float*)d_in[15];
    const float* mlp_b1  = (const float*)d_in[16];
    const float* mlp_w2  = (const float*)d_in[17];
    const float* mlp_b2  = (const float*)d_in[18];
    const float* w_last  = (const float*)d_in[19];
    const float* b_last  = (const float*)d_in[20];
    float* out = (float*)d_out;

    float *x, *xd, *gX, *gY, *bre, *bim, *gf, *h1, *h2, *spec;
    cudaGetSymbolAddress((void**)&x,   g_x);
    cudaGetSymbolAddress((void**)&xd,  g_xd);
    cudaGetSymbolAddress((void**)&gX,  g_gX);
    cudaGetSymbolAddress((void**)&gY,  g_gY);
    cudaGetSymbolAddress((void**)&bre, g_bre);
    cudaGetSymbolAddress((void**)&bim, g_bim);
    cudaGetSymbolAddress((void**)&gf,  g_gf);
    cudaGetSymbolAddress((void**)&h1,  g_h1);
    cudaGetSymbolAddress((void**)&h2,  g_h2);
    cudaGetSymbolAddress((void**)&spec, g_spec);

    static bool attr_set = false;
    if (!attr_set) {
        cudaFuncSetAttribute(gemm_k, cudaFuncAttributeMaxDynamicSharedMemorySize,
                             98304);
        attr_set = true;
    }
    const int GEMM_SMEM = 98304;
    const int n4 = NC / 4;            // 5,120,000 float4
    const int zgrid = (n4 + 255) / 256;

    // x = x_in @ w_first + b_first
    first_k<<<ROWS_TOT / 32, 128>>>(x_in, w_first, b_first, x);

    for (int i = 0; i < 4; i++) {
        // --- spectral diffusion ---
        zero_k<<<(B_ * K_ * CW_ / 4 + 255) / 256, 256>>>((float4*)spec, B_ * K_ * CW_ / 4);
        spec_fwd_k<<<dim3((N_ + 511) / 512, B_), 256>>>(evecs, x, mass, spec, 512);
        spec_scale_k<<<256, 256>>>(spec, evals, dtim + i * CW_);
        // xd[b] = evecs[b] @ spec[b]
        gemm_k<<<dim3(N_ / 64, B_), 256, GEMM_SMEM>>>(
            evecs, spec, 1.f, nullptr, nullptr, 0.f, nullptr, nullptr, 0.f,
            nullptr, nullptr, xd, N_, 1, EPI_NONE, K_ * CW_);

        // --- sparse gradients ---
        zero_k<<<zgrid, 256>>>((float4*)gX, n4);
        zero_k<<<zgrid, 256>>>((float4*)gY, n4);
        spmm_k<<<dim3(E_ / SP_EPB, B_), 128>>>(rows, cols, gradX, gradY, xd, gX, gY);

        // --- spatial gradient features ---
        const float* Are = A_re + (long)i * CW_ * CW_;
        const float* Aim = A_im + (long)i * CW_ * CW_;
        gemm_k<<<dim3(ROWS_TOT / 64, 1), 256, GEMM_SMEM>>>(
            gX, Are, 1.f, gY, Aim, -1.f, nullptr, nullptr, 0.f,
            nullptr, nullptr, bre, ROWS_TOT, 2, EPI_NONE, 0);
        gemm_k<<<dim3(ROWS_TOT / 64, 1), 256, GEMM_SMEM>>>(
            gY, Are, 1.f, gX, Aim, 1.f, nullptr, nullptr, 0.f,
            nullptr, nullptr, bim, ROWS_TOT, 2, EPI_NONE, 0);
        gradfeat_k<<<zgrid, 256>>>((float4*)gX, (float4*)gY, (float4*)bre,
                                   (float4*)bim, (float4*)gf, n4);

        // --- MiniMLP + residual ---
        const float* W0 = mlp_w0 + (long)i * 3 * CW_ * CW_;
        gemm_k<<<dim3(ROWS_TOT / 64, 1), 256, GEMM_SMEM>>>(
            x, W0, 1.f, xd, W0 + CW_ * CW_, 1.f, gf, W0 + 2 * CW_ * CW_, 1.f,
            mlp_b0 + i * CW_, nullptr, h1, ROWS_TOT, 3, EPI_BRELU, 0);
        gemm_k<<<dim3(ROWS_TOT / 64, 1), 256, GEMM_SMEM>>>(
            h1, mlp_w1 + (long)i * CW_ * CW_, 1.f, nullptr, nullptr, 0.f,
            nullptr, nullptr, 0.f, mlp_b1 + i * CW_, nullptr, h2,
            ROWS_TOT, 1, EPI_BRELU, 0);
        gemm_k<<<dim3(ROWS_TOT / 64, 1), 256, GEMM_SMEM>>>(
            h2, mlp_w2 + (long)i * CW_ * CW_, 1.f, nullptr, nullptr, 0.f,
            nullptr, nullptr, 0.f, mlp_b2 + i * CW_, x, x,
            ROWS_TOT, 1, EPI_BRES, 0);
    }

    // out = x @ w_last + b_last
    last_k<<<ROWS_TOT / 32, 128>>>(x, w_last, b_last, out);
}

// round 4
// speedup vs baseline: 1.3113x; 1.3113x over previous
#include <cuda_runtime.h>
#include <cuda_bf16.h>
#include <math.h>

#define B_   4
#define N_   40000
#define E_   240000
#define CW_  128
#define ROWS_TOT (B_*N_)          // 160000
#define NC   (B_*N_*CW_)          // 20,480,000 floats per buffer

// padded bf16 tile geometry: 128 rows x 136 cols (k), 272 B/row
#define PADK 136
#define IMG_U32 8704              // one 128x136 bf16 image = 34816 B = 8704 u32
#define SLOT_U32 (2*IMG_U32)      // hi + lo = 17408 u32 = 69632 B

// ---- scratch (static __device__, allocation-free per harness rules) ----
__device__ float g_x  [NC];
__device__ float g_xd [NC];
__device__ float g_gX [NC];
__device__ float g_gY [NC];
__device__ float g_gf [NC];
__device__ float g_h1 [NC];
__device__ float g_h2 [NC];
__device__ float g_spec[B_*128*128];
__device__ unsigned int g_wimg[4*SLOT_U32];

enum { EPI2_NONE = 0, EPI2_RELU = 1, EPI2_RES = 2, EPI2_GRAD = 3 };

// ===========================================================================
// helpers (baseline PTX only: ldmatrix + mma.sync, no 'a'-gated features)
// ===========================================================================
__device__ __forceinline__ unsigned smem_u32(const void* p) {
    unsigned a;
    asm("{ .reg .u64 t; cvta.to.shared.u64 t, %1; cvt.u32.u64 %0, t; }"
        : "=r"(a) : "l"(p));
    return a;
}
__device__ __forceinline__ void ldsm4(unsigned* r, unsigned addr) {
    asm volatile("ldmatrix.sync.aligned.m8n8.x4.shared.b16 {%0,%1,%2,%3}, [%4];"
                 : "=r"(r[0]), "=r"(r[1]), "=r"(r[2]), "=r"(r[3]) : "r"(addr));
}
__device__ __forceinline__ void mma_bf16(float* c, const unsigned* a,
                                         unsigned b0, unsigned b1) {
    asm volatile(
        "mma.sync.aligned.m16n8k16.row.col.f32.bf16.bf16.f32 "
        "{%0,%1,%2,%3}, {%4,%5,%6,%7}, {%8,%9}, {%0,%1,%2,%3};"
        : "+f"(c[0]), "+f"(c[1]), "+f"(c[2]), "+f"(c[3])
        : "r"(a[0]), "r"(a[1]), "r"(a[2]), "r"(a[3]), "r"(b0), "r"(b1));
}
__device__ __forceinline__ unsigned pack_bf(float a, float b) {
    __nv_bfloat162 t = __floats2bfloat162_rn(a, b);
    return *reinterpret_cast<unsigned*>(&t);
}
// split a float pair into bf16 hi pair + bf16 lo (residual) pair
__device__ __forceinline__ void split2(float a, float b, unsigned& h, unsigned& l) {
    float ah = __bfloat162float(__float2bfloat16_rn(a));
    float bh = __bfloat162float(__float2bfloat16_rn(b));
    h = pack_bf(a, b);
    l = pack_bf(a - ah, b - bh);
}

// ===========================================================================
// zero
// ===========================================================================
__global__ void zero_k(float4* __restrict__ p, int n4) {
    int i = blockIdx.x * blockDim.x + threadIdx.x;
    if (i < n4) p[i] = make_float4(0.f, 0.f, 0.f, 0.f);
}

// ===========================================================================
// first / last
// ===========================================================================
__global__ __launch_bounds__(128) void first_k(
    const float* __restrict__ x_in, const float* __restrict__ w,
    const float* __restrict__ bias, float* __restrict__ x)
{
    __shared__ float sW[6 * 128];
    __shared__ float sB[128];
    __shared__ float sX[32 * 6];
    int tid = threadIdx.x;
    long m0 = (long)blockIdx.x * 32;
    for (int idx = tid; idx < 768; idx += 128) sW[idx] = __ldg(w + idx);
    sB[tid] = __ldg(bias + tid);
    for (int idx = tid; idx < 192; idx += 128) sX[idx] = __ldg(x_in + m0 * 6 + idx);
    __syncthreads();
    #pragma unroll 4
    for (int r = 0; r < 32; r++) {
        float a = sB[tid];
        #pragma unroll
        for (int t = 0; t < 6; t++) a += sX[r * 6 + t] * sW[t * 128 + tid];
        x[(m0 + r) * 128 + tid] = a;
    }
}

__global__ __launch_bounds__(128) void last_k(
    const float* __restrict__ x, const float* __restrict__ w,
    const float* __restrict__ bias, float* __restrict__ out)
{
    __shared__ float sX[32 * 128];
    __shared__ float sW[128 * 3];
    __shared__ float sB[3];
    int tid = threadIdx.x;
    long m0 = (long)blockIdx.x * 32;
    for (int idx = tid; idx < 384; idx += 128) sW[idx] = __ldg(w + idx);
    if (tid < 3) sB[tid] = __ldg(bias + tid);
    for (int idx = tid; idx < 1024; idx += 128)
        ((float4*)sX)[idx] = __ldg((const float4*)(x + m0 * 128) + idx);
    __syncthreads();
    if (tid < 96) {
        int r = tid / 3, c = tid % 3;
        float a = sB[c];
        #pragma unroll 8
        for (int k = 0; k < 128; k++) a += sX[r * 128 + k] * sW[k * 3 + c];
        out[(m0 + r) * 3 + c] = a;
    }
}

// ===========================================================================
// spectral forward (FFMA outer-product reduction)
// ===========================================================================
#define SF_TS 16
__global__ __launch_bounds__(256) void spec_fwd_k(
    const float* __restrict__ evecs, const float* __restrict__ x,
    const float* __restrict__ mass, float* __restrict__ spec, int chunk)
{
    __shared__ float sE[SF_TS][128];
    __shared__ float sX[SF_TS][128];
    int b  = blockIdx.y;
    int n0 = blockIdx.x * chunk;
    int n1 = min(n0 + chunk, N_);
    int tid = threadIdx.x;
    int cg = tid & 15, kg = tid >> 4;
    int k0 = kg * 8, c0 = cg * 8;
    float acc[8][8];
    #pragma unroll
    for (int i = 0; i < 8; i++)
        #pragma unroll
        for (int j = 0; j < 8; j++) acc[i][j] = 0.f;

    const float* Eb = evecs + (long)b * N_ * 128;
    const float* Xb = x     + (long)b * N_ * 128;
    const float* Mb = mass  + (long)b * N_;

    for (int nt = n0; nt < n1; nt += SF_TS) {
        for (int idx = tid; idx < SF_TS * 32; idx += 256) {
            int r = idx >> 5, q = idx & 31;
            int n = nt + r;
            float4 e4 = make_float4(0.f, 0.f, 0.f, 0.f);
            float4 x4 = make_float4(0.f, 0.f, 0.f, 0.f);
            if (n < n1) {
                e4 = __ldg((const float4*)(Eb + (long)n * 128) + q);
                float m = __ldg(Mb + n);
                x4 = __ldg((const float4*)(Xb + (long)n * 128) + q);
                x4.x *= m; x4.y *= m; x4.z *= m; x4.w *= m;
            }
            ((float4*)sE[r])[q] = e4;
            ((float4*)sX[r])[q] = x4;
        }
        __syncthreads();
        #pragma unroll 4
        for (int t = 0; t < SF_TS; t++) {
            float4 ea = *(const float4*)&sE[t][k0];
            float4 eb = *(const float4*)&sE[t][k0 + 4];
            float4 xa = *(const float4*)&sX[t][c0];
            float4 xb = *(const float4*)&sX[t][c0 + 4];
            float e[8] = {ea.x, ea.y, ea.z, ea.w, eb.x, eb.y, eb.z, eb.w};
            float v[8] = {xa.x, xa.y, xa.z, xa.w, xb.x, xb.y, xb.z, xb.w};
            #pragma unroll
            for (int i = 0; i < 8; i++)
                #pragma unroll
                for (int j = 0; j < 8; j++) acc[i][j] += e[i] * v[j];
        }
        __syncthreads();
    }
    float* Sb = spec + (long)b * 128 * 128;
    #pragma unroll
    for (int i = 0; i < 8; i++)
        #pragma unroll
        for (int j = 0; j < 8; j++)
            atomicAdd(Sb + (long)(k0 + i) * 128 + (c0 + j), acc[i][j]);
}

// ===========================================================================
// W-image prep: transposed (Wt[n][k]), hi/lo split, padded row (136 k) bf16.
// Image layout matches the gemm smem W tile exactly (straight uint4 copy).
// hi u32 index: n*68 + k/2 ; lo at +IMG_U32.
// ===========================================================================
__global__ __launch_bounds__(256) void prep_spec_k(
    const float* __restrict__ spec, const float* __restrict__ evals,
    const float* __restrict__ dt, unsigned* __restrict__ wimg)
{
    int b = blockIdx.x;
    const float* W  = spec  + (long)b * 16384;   // [k][c]
    const float* ev = evals + b * 128;
    unsigned* hi = wimg + (long)b * SLOT_U32;
    unsigned* lo = hi + IMG_U32;
    int tid = threadIdx.x;
    for (int idx = tid; idx < 8192; idx += 256) {
        int n = idx >> 6, kp = idx & 63;        // n = out channel c, kp = k pair
        int k = kp * 2;
        float d = __ldg(dt + n);
        float v0 = __ldg(W + (k + 0) * 128 + n) * expf(-__ldg(ev + k + 0) * d);
        float v1 = __ldg(W + (k + 1) * 128 + n) * expf(-__ldg(ev + k + 1) * d);
        unsigned h, l;
        split2(v0, v1, h, l);
        hi[n * 68 + kp] = h;
        lo[n * 68 + kp] = l;
    }
}

__global__ __launch_bounds__(256) void prep_w_k(
    const float* __restrict__ W0, float s0, const float* __restrict__ W1, float s1,
    const float* __restrict__ W2, float s2, const float* __restrict__ W3, float s3,
    unsigned* __restrict__ wimg)
{
    int slot = blockIdx.x;
    const float* W = (slot == 0) ? W0 : (slot == 1) ? W1 : (slot == 2) ? W2 : W3;
    float s = (slot == 0) ? s0 : (slot == 1) ? s1 : (slot == 2) ? s2 : s3;
    unsigned* hi = wimg + (long)slot * SLOT_U32;
    unsigned* lo = hi + IMG_U32;
    int tid = threadIdx.x;
    for (int idx = tid; idx < 8192; idx += 256) {
        int n = idx >> 6, kp = idx & 63;
        int k = kp * 2;
        float v0 = __ldg(W + (k + 0) * 128 + n) * s;
        float v1 = __ldg(W + (k + 1) * 128 + n) * s;
        unsigned h, l;
        split2(v0, v1, h, l);
        hi[n * 68 + kp] = h;
        lo[n * 68 + kp] = l;
    }
}

// ===========================================================================
// mma.sync bf16x3 GEMM: C[m,c] = epi( sum_jin sum_d A_jin[m,:] @ Wt_slot )
// tile 128x128x128, 8 warps (4m x 2n), warp tile 32x64.
// ND accumulators (Breal/Bimag for the rotation stage).
// smem: sAh | sAl | per-d (sWh | sWl); each image 34816 B.
// ===========================================================================
template <int ND>
__global__ __launch_bounds__(256, 1) void gemm_mma(
    const float* __restrict__ A0, const float* __restrict__ A1,
    const float* __restrict__ A2, const unsigned* __restrict__ wimg,
    int M, int num_in, int pbs, int epi,
    const float* __restrict__ bias, const float* __restrict__ resid,
    const float* __restrict__ gXp, const float* __restrict__ gYp,
    float* __restrict__ C)
{
    extern __shared__ char sb[];
    unsigned sbase = smem_u32(sb);

    int tid = threadIdx.x, wid = tid >> 5, lid = tid & 31;
    int zb = blockIdx.y;
    long aoff = (long)zb * M * 128;
    int m0 = blockIdx.x * 128;

    float acc[ND][2][8][4];
    #pragma unroll
    for (int d = 0; d < ND; d++)
        #pragma unroll
        for (int mt = 0; mt < 2; mt++)
            #pragma unroll
            for (int nt = 0; nt < 8; nt++)
                #pragma unroll
                for (int j = 0; j < 4; j++) acc[d][mt][nt][j] = 0.f;

    const float* As[3] = {A0, A1, A2};

    // per-lane ldmatrix address offsets (within a tile image)
    int q = lid >> 3, r = lid & 7;
    int mwarp = wid >> 1, nwarp = wid & 1;
    // A: quads {0,1,2,3} -> (row+0,k0),(row+8,k0),(row+0,k0+8),(row+8,k0+8)
    int a_row_in = (q & 1) * 8 + r;
    int a_koff   = (q >> 1) * 8;
    // B: quads -> (n+0,k0),(n+0,k0+8),(n+8,k0),(n+8,k0+8)
    int b_row_in = (q >> 1) * 8 + r;
    int b_koff   = (q & 1) * 8;

    unsigned sA  = sbase;
    unsigned sAl = sbase + 34816u;
    unsigned sW0 = sbase + 2u * 34816u;

    // byte offsets: row*272 + k*2
    unsigned aoffb[2], boffb[4];
    #pragma unroll
    for (int mt = 0; mt < 2; mt++)
        aoffb[mt] = (unsigned)((mwarp * 32 + mt * 16 + a_row_in) * 272 + a_koff * 2);
    #pragma unroll
    for (int np = 0; np < 4; np++)
        boffb[np] = (unsigned)((nwarp * 64 + np * 16 + b_row_in) * 272 + b_koff * 2);

    for (int jin = 0; jin < num_in; jin++) {
        __syncthreads();
        // copy ND W slots (hi+lo contiguous per slot)
        #pragma unroll
        for (int d = 0; d < ND; d++) {
            int slot = zb * pbs + jin * ND + d;
            const uint4* src = (const uint4*)(wimg + (long)slot * SLOT_U32);
            uint4* dst = (uint4*)(sb + 2 * 34816 + d * 69632);
            #pragma unroll 4
            for (int idx = tid; idx < 4352; idx += 256) dst[idx] = __ldg(src + idx);
        }
        // load + split A tile (fp32 -> bf16 hi/lo, padded rows)
        const float* A = As[jin] + aoff;
        #pragma unroll 4
        for (int idx = tid; idx < 4096; idx += 256) {
            int rr = idx >> 5, qq = idx & 31;
            int grow = m0 + rr;
            float4 v = make_float4(0.f, 0.f, 0.f, 0.f);
            if (grow < M) v = __ldg((const float4*)(A + (long)grow * 128) + qq);
            unsigned h0, l0, h1, l1;
            split2(v.x, v.y, h0, l0);
            split2(v.z, v.w, h1, l1);
            unsigned off = rr * 272 + qq * 8;
            *(uint2*)(sb + off)         = make_uint2(h0, h1);
            *(uint2*)(sb + 34816 + off) = make_uint2(l0, l1);
        }
        __syncthreads();

        // compute: 8 k-steps of 16
        #pragma unroll
        for (int ks = 0; ks < 8; ks++) {
            unsigned kb = ks * 32;   // k0 * 2 bytes
            unsigned ah[2][4], al[2][4];
            #pragma unroll
            for (int mt = 0; mt < 2; mt++) {
                ldsm4(ah[mt], sA  + aoffb[mt] + kb);
                ldsm4(al[mt], sAl + aoffb[mt] + kb);
            }
            #pragma unroll
            for (int d = 0; d < ND; d++) {
                unsigned wHi = sW0 + d * 69632u;
                unsigned wLo = wHi + 34816u;
                #pragma unroll
                for (int np = 0; np < 4; np++) {
                    unsigned bh[4], bl[4];
                    ldsm4(bh, wHi + boffb[np] + kb);
                    ldsm4(bl, wLo + boffb[np] + kb);
                    #pragma unroll
                    for (int mt = 0; mt < 2; mt++) {
                        float* c0 = acc[d][mt][np * 2];
                        float* c1 = acc[d][mt][np * 2 + 1];
                        mma_bf16(c0, ah[mt], bh[0], bh[1]);
                        mma_bf16(c0, al[mt], bh[0], bh[1]);
                        mma_bf16(c0, ah[mt], bl[0], bl[1]);
                        mma_bf16(c1, ah[mt], bh[2], bh[3]);
                        mma_bf16(c1, al[mt], bh[2], bh[3]);
                        mma_bf16(c1, ah[mt], bl[2], bl[3]);
                    }
                }
            }
        }
    }

    // epilogue
    int colg = (lid & 3) * 2;
    int rowg = lid >> 2;
    #pragma unroll
    for (int mt = 0; mt < 2; mt++) {
        #pragma unroll
        for (int h = 0; h < 2; h++) {
            int row = m0 + mwarp * 32 + mt * 16 + rowg + h * 8;
            if (row >= M) continue;
            long rbase = aoff + (long)row * 128;
            #pragma unroll
            for (int nt = 0; nt < 8; nt++) {
                int col = nwarp * 64 + nt * 8 + colg;
                float v0 = acc[0][mt][nt][h * 2];
                float v1 = acc[0][mt][nt][h * 2 + 1];
                float o0, o1;
                if (epi == EPI2_GRAD) {
                    float w0 = acc[1][mt][nt][h * 2];
                    float w1 = acc[1][mt][nt][h * 2 + 1];
                    float2 gx = __ldg((const float2*)(gXp + rbase + col));
                    float2 gy = __ldg((const float2*)(gYp + rbase + col));
                    o0 = tanhf(gx.x * v0 + gy.x * w0);
                    o1 = tanhf(gx.y * v1 + gy.y * w1);
                } else if (epi == EPI2_NONE) {
                    o0 = v0; o1 = v1;
                } else {
                    float2 bv = __ldg((const float2*)(bias + col));
                    o0 = v0 + bv.x; o1 = v1 + bv.y;
                    if (epi == EPI2_RELU) {
                        o0 = fmaxf(o0, 0.f); o1 = fmaxf(o1, 0.f);
                    } else {   // EPI2_RES
                        float2 rv = __ldg((const float2*)(resid + rbase + col));
                        o0 += rv.x; o1 += rv.y;
                    }
                }
                *(float2*)(C + rbase + col) = make_float2(o0, o1);
            }
        }
    }
}

// ===========================================================================
// SPMM scatter
// ===========================================================================
#define SP_EPB 8
__global__ __launch_bounds__(128) void spmm_k(
    const int* __restrict__ rows, const int* __restrict__ cols,
    const float* __restrict__ gxv, const float* __restrict__ gyv,
    const float* __restrict__ xd, float* __restrict__ gX, float* __restrict__ gY)
{
    int b = blockIdx.y;
    int c = threadIdx.x;
    int e0 = blockIdx.x * SP_EPB;
    const float* xb = xd + (long)b * N_ * 128;
    float* gxb = gX + (long)b * N_ * 128;
    float* gyb = gY + (long)b * N_ * 128;
    #pragma unroll
    for (int q = 0; q < SP_EPB; q++) {
        int e = e0 + q;
        int r   = __ldg(rows + e);
        int col = __ldg(cols + e);
        float vx = __ldg(gxv + (long)b * E_ + e);
        float vy = __ldg(gyv + (long)b * E_ + e);
        float xv = __ldg(xb + (long)col * 128 + c);
        atomicAdd(gxb + (long)r * 128 + c, vx * xv);
        atomicAdd(gyb + (long)r * 128 + c, vy * xv);
    }
}

// ===========================================================================
extern "C" void kernel_launch(void* const* d_in, const int* in_sizes, int n_in,
                              void* d_out, int out_size)
{
    const float* x_in    = (const float*)d_in[0];
    const float* mass    = (const float*)d_in[1];
    const float* evals   = (const float*)d_in[2];
    const float* evecs   = (const float*)d_in[3];
    const int*   rows    = (const int*)  d_in[4];
    const int*   cols    = (const int*)  d_in[5];
    const float* gradX   = (const float*)d_in[6];
    const float* gradY   = (const float*)d_in[7];
    const float* w_first = (const float*)d_in[8];
    const float* b_first = (const float*)d_in[9];
    const float* dtim    = (const float*)d_in[10];
    const float* A_re    = (const float*)d_in[11];
    const float* A_im    = (const float*)d_in[12];
    const float* mlp_w0  = (const float*)d_in[13];
    const float* mlp_b0  = (const float*)d_in[14];
    const float* mlp_w1  = (const float*)d_in[15];
    const float* mlp_b1  = (const float*)d_in[16];
    const float* mlp_w2  = (const float*)d_in[17];
    const float* mlp_b2  = (const float*)d_in[18];
    const float* w_last  = (const float*)d_in[19];
    const float* b_last  = (const float*)d_in[20];
    float* out = (float*)d_out;

    float *x, *xd, *gX, *gY, *gf, *h1, *h2, *spec;
    unsigned* wimg;
    cudaGetSymbolAddress((void**)&x,    g_x);
    cudaGetSymbolAddress((void**)&xd,   g_xd);
    cudaGetSymbolAddress((void**)&gX,   g_gX);
    cudaGetSymbolAddress((void**)&gY,   g_gY);
    cudaGetSymbolAddress((void**)&gf,   g_gf);
    cudaGetSymbolAddress((void**)&h1,   g_h1);
    cudaGetSymbolAddress((void**)&h2,   g_h2);
    cudaGetSymbolAddress((void**)&spec, g_spec);
    cudaGetSymbolAddress((void**)&wimg, g_wimg);

    const int SMEM1 = 2 * 34816 + 1 * 69632;   // 139,264
    const int SMEM2 = 2 * 34816 + 2 * 69632;   // 208,896
    cudaFuncSetAttribute(gemm_mma<1>, cudaFuncAttributeMaxDynamicSharedMemorySize, SMEM1);
    cudaFuncSetAttribute(gemm_mma<2>, cudaFuncAttributeMaxDynamicSharedMemorySize, SMEM2);

    const int n4 = NC / 4;
    const int zgrid = (n4 + 255) / 256;
    const float* nullf = nullptr;

    first_k<<<ROWS_TOT / 32, 128>>>(x_in, w_first, b_first, x);

    for (int i = 0; i < 4; i++) {
        // --- spectral diffusion ---
        zero_k<<<64, 256>>>((float4*)spec, B_ * 128 * 128 / 4);
        spec_fwd_k<<<dim3((N_ + 511) / 512, B_), 256>>>(evecs, x, mass, spec, 512);
        prep_spec_k<<<4, 256>>>(spec, evals, dtim + i * CW_, wimg);
        gemm_mma<1><<<dim3((N_ + 127) / 128, B_), 256, SMEM1>>>(
            evecs, nullf, nullf, wimg, N_, 1, 1, EPI2_NONE,
            nullf, nullf, nullf, nullf, xd);

        // --- sparse gradients ---
        zero_k<<<zgrid, 256>>>((float4*)gX, n4);
        zero_k<<<zgrid, 256>>>((float4*)gY, n4);
        spmm_k<<<dim3(E_ / SP_EPB, B_), 128>>>(rows, cols, gradX, gradY, xd, gX, gY);

        // --- rotation + tanh gradient features (fused, dual accumulators) ---
        const float* Are = A_re + (long)i * CW_ * CW_;
        const float* Aim = A_im + (long)i * CW_ * CW_;
        // slots: jin0(gX): d0=Are(+1), d1=Aim(+1); jin1(gY): d0=Aim(-1), d1=Are(+1)
        prep_w_k<<<4, 256>>>(Are, 1.f, Aim, 1.f, Aim, -1.f, Are, 1.f, wimg);
        gemm_mma<2><<<dim3(ROWS_TOT / 128, 1), 256, SMEM2>>>(
            gX, gY, nullf, wimg, ROWS_TOT, 2, 4, EPI2_GRAD,
            nullf, nullf, gX, gY, gf);

        // --- MiniMLP + residual ---
        const float* W0 = mlp_w0 + (long)i * 3 * CW_ * CW_;
        prep_w_k<<<3, 256>>>(W0, 1.f, W0 + 16384, 1.f, W0 + 32768, 1.f, nullf, 0.f, wimg);
        gemm_mma<1><<<dim3(ROWS_TOT / 128, 1), 256, SMEM1>>>(
            x, xd, gf, wimg, ROWS_TOT, 3, 3, EPI2_RELU,
            mlp_b0 + i * CW_, nullf, nullf, nullf, h1);

        prep_w_k<<<1, 256>>>(mlp_w1 + (long)i * CW_ * CW_, 1.f, nullf, 0.f,
                             nullf, 0.f, nullf, 0.f, wimg);
        gemm_mma<1><<<dim3(ROWS_TOT / 128, 1), 256, SMEM1>>>(
            h1, nullf, nullf, wimg, ROWS_TOT, 1, 1, EPI2_RELU,
            mlp_b1 + i * CW_, nullf, nullf, nullf, h2);

        prep_w_k<<<1, 256>>>(mlp_w2 + (long)i * CW_ * CW_, 1.f, nullf, 0.f,
                             nullf, 0.f, nullf, 0.f, wimg);
        gemm_mma<1><<<dim3(ROWS_TOT / 128, 1), 256, SMEM1>>>(
            h2, nullf, nullf, wimg, ROWS_TOT, 1, 1, EPI2_RES,
            mlp_b2 + i * CW_, x, nullf, nullf, x);
    }

    last_k<<<ROWS_TOT / 32, 128>>>(x, w_last, b_last, out);
}

// round 6
// speedup vs baseline: 1.4492x; 1.1052x over previous
#include <cuda_runtime.h>
#include <cuda_bf16.h>
#include <math.h>

#define B_   4
#define N_   40000
#define E_   240000
#define CW_  128
#define ROWS_TOT (B_*N_)          // 160000
#define NC   (B_*N_*CW_)          // 20,480,000 floats per buffer

// padded bf16 tile geometry: 128 rows x 136 cols (k), 272 B/row
#define IMG_U32 8704              // one 128x136 bf16 image = 34816 B = 8704 u32
#define SLOT_U32 (2*IMG_U32)      // hi + lo = 17408 u32 = 69632 B

// ---- scratch (static __device__, allocation-free per harness rules) ----
__device__ float g_x  [NC];
__device__ float g_xd [NC];
__device__ float g_gX [NC];
__device__ float g_gY [NC];
__device__ float g_gf [NC];
__device__ float g_h1 [NC];
__device__ float g_h2 [NC];
__device__ float g_spec[B_*128*128];
__device__ unsigned int g_wimg[4*SLOT_U32];
__device__ int g_rowptr[N_ + 1];
__device__ int g_cursor[N_];
__device__ int g_perm[E_];

enum { EPI2_NONE = 0, EPI2_RELU = 1, EPI2_RES = 2, EPI2_GRAD = 3 };

// ===========================================================================
// helpers (baseline PTX only: ldmatrix + mma.sync + cp.async)
// ===========================================================================
__device__ __forceinline__ unsigned smem_u32(const void* p) {
    unsigned a;
    asm("{ .reg .u64 t; cvta.to.shared.u64 t, %1; cvt.u32.u64 %0, t; }"
        : "=r"(a) : "l"(p));
    return a;
}
__device__ __forceinline__ void ldsm4(unsigned* r, unsigned addr) {
    asm volatile("ldmatrix.sync.aligned.m8n8.x4.shared.b16 {%0,%1,%2,%3}, [%4];"
                 : "=r"(r[0]), "=r"(r[1]), "=r"(r[2]), "=r"(r[3]) : "r"(addr));
}
__device__ __forceinline__ void mma_bf16(float* c, const unsigned* a,
                                         unsigned b0, unsigned b1) {
    asm volatile(
        "mma.sync.aligned.m16n8k16.row.col.f32.bf16.bf16.f32 "
        "{%0,%1,%2,%3}, {%4,%5,%6,%7}, {%8,%9}, {%0,%1,%2,%3};"
        : "+f"(c[0]), "+f"(c[1]), "+f"(c[2]), "+f"(c[3])
        : "r"(a[0]), "r"(a[1]), "r"(a[2]), "r"(a[3]), "r"(b0), "r"(b1));
}
__device__ __forceinline__ void cp16(unsigned saddr, const void* g) {
    asm volatile("cp.async.cg.shared.global [%0], [%1], 16;"
                 :: "r"(saddr), "l"(g));
}
#define CP_COMMIT() asm volatile("cp.async.commit_group;" ::: "memory")
#define CP_WAIT0()  asm volatile("cp.async.wait_group 0;" ::: "memory")

__device__ __forceinline__ unsigned pack_bf(float a, float b) {
    __nv_bfloat162 t = __floats2bfloat162_rn(a, b);
    return *reinterpret_cast<unsigned*>(&t);
}
__device__ __forceinline__ void split2(float a, float b, unsigned& h, unsigned& l) {
    float ah = __bfloat162float(__float2bfloat16_rn(a));
    float bh = __bfloat162float(__float2bfloat16_rn(b));
    h = pack_bf(a, b);
    l = pack_bf(a - ah, b - bh);
}

// ===========================================================================
// zero (float4 / int variants)
// ===========================================================================
__global__ void zero_k(float4* __restrict__ p, int n4) {
    int i = blockIdx.x * blockDim.x + threadIdx.x;
    if (i < n4) p[i] = make_float4(0.f, 0.f, 0.f, 0.f);
}
__global__ void zero_i(int* __restrict__ p, int n) {
    int i = blockIdx.x * blockDim.x + threadIdx.x;
    if (i < n) p[i] = 0;
}

// ===========================================================================
// CSR build: hist -> scan -> perm
// ===========================================================================
__global__ void hist_k(const int* __restrict__ rows, int* __restrict__ rowptr) {
    int e = blockIdx.x * blockDim.x + threadIdx.x;
    if (e < E_) atomicAdd(&rowptr[__ldg(rows + e) + 1], 1);
}

// single-block inclusive scan over rowptr[1..N_]; each thread owns 40 entries
__global__ __launch_bounds__(1024) void scan_k(int* __restrict__ rowptr) {
    __shared__ int sums[1024];
    int t = threadIdx.x;
    const int PER = (N_ + 1023) / 1024;     // 40
    int base = 1 + t * PER;
    int s = 0;
    #pragma unroll 4
    for (int i = 0; i < PER; i++) {
        int idx = base + i;
        if (idx <= N_) s += rowptr[idx];
    }
    sums[t] = s;
    __syncthreads();
    // Hillis-Steele inclusive scan
    for (int off = 1; off < 1024; off <<= 1) {
        int v = (t >= off) ? sums[t - off] : 0;
        __syncthreads();
        sums[t] += v;
        __syncthreads();
    }
    int run = (t > 0) ? sums[t - 1] : 0;
    #pragma unroll 4
    for (int i = 0; i < PER; i++) {
        int idx = base + i;
        if (idx <= N_) {
            run += rowptr[idx];
            rowptr[idx] = run;
        }
    }
    if (t == 0) rowptr[0] = 0;
}

__global__ void cursor_k(const int* __restrict__ rowptr, int* __restrict__ cur) {
    int r = blockIdx.x * blockDim.x + threadIdx.x;
    if (r < N_) cur[r] = rowptr[r];
}
__global__ void perm_k(const int* __restrict__ rows, int* __restrict__ cur,
                       int* __restrict__ perm) {
    int e = blockIdx.x * blockDim.x + threadIdx.x;
    if (e < E_) {
        int pos = atomicAdd(&cur[__ldg(rows + e)], 1);
        perm[pos] = e;
    }
}

// ===========================================================================
// gather SPMM: per (row, channel) accumulate edges, no atomics
// ===========================================================================
#define SG_ROWS 8
__global__ __launch_bounds__(128) void spmm_gather_k(
    const int* __restrict__ rowptr, const int* __restrict__ perm,
    const int* __restrict__ cols,
    const float* __restrict__ gxv, const float* __restrict__ gyv,
    const float* __restrict__ xd, float* __restrict__ gX, float* __restrict__ gY)
{
    int b = blockIdx.y;
    int c = threadIdx.x;
    int r0 = blockIdx.x * SG_ROWS;
    const float* xb  = xd + (long)b * N_ * 128;
    const float* gxb = gxv + (long)b * E_;
    const float* gyb = gyv + (long)b * E_;
    float* oX = gX + (long)b * N_ * 128;
    float* oY = gY + (long)b * N_ * 128;
    #pragma unroll
    for (int rr = 0; rr < SG_ROWS; rr++) {
        int r = r0 + rr;
        int j    = __ldg(rowptr + r);
        int jend = __ldg(rowptr + r + 1);
        float ax = 0.f, ay = 0.f;
        for (; j + 1 < jend; j += 2) {
            int e0 = __ldg(perm + j),     e1 = __ldg(perm + j + 1);
            int c0 = __ldg(cols + e0),    c1 = __ldg(cols + e1);
            float x0 = __ldg(xb + (long)c0 * 128 + c);
            float x1 = __ldg(xb + (long)c1 * 128 + c);
            ax += __ldg(gxb + e0) * x0 + __ldg(gxb + e1) * x1;
            ay += __ldg(gyb + e0) * x0 + __ldg(gyb + e1) * x1;
        }
        if (j < jend) {
            int e0 = __ldg(perm + j);
            int c0 = __ldg(cols + e0);
            float x0 = __ldg(xb + (long)c0 * 128 + c);
            ax += __ldg(gxb + e0) * x0;
            ay += __ldg(gyb + e0) * x0;
        }
        oX[(long)r * 128 + c] = ax;
        oY[(long)r * 128 + c] = ay;
    }
}

// ===========================================================================
// first / last
// ===========================================================================
__global__ __launch_bounds__(128) void first_k(
    const float* __restrict__ x_in, const float* __restrict__ w,
    const float* __restrict__ bias, float* __restrict__ x)
{
    __shared__ float sW[6 * 128];
    __shared__ float sB[128];
    __shared__ float sX[32 * 6];
    int tid = threadIdx.x;
    long m0 = (long)blockIdx.x * 32;
    for (int idx = tid; idx < 768; idx += 128) sW[idx] = __ldg(w + idx);
    sB[tid] = __ldg(bias + tid);
    for (int idx = tid; idx < 192; idx += 128) sX[idx] = __ldg(x_in + m0 * 6 + idx);
    __syncthreads();
    #pragma unroll 4
    for (int r = 0; r < 32; r++) {
        float a = sB[tid];
        #pragma unroll
        for (int t = 0; t < 6; t++) a += sX[r * 6 + t] * sW[t * 128 + tid];
        x[(m0 + r) * 128 + tid] = a;
    }
}

__global__ __launch_bounds__(128) void last_k(
    const float* __restrict__ x, const float* __restrict__ w,
    const float* __restrict__ bias, float* __restrict__ out)
{
    __shared__ float sX[32 * 128];
    __shared__ float sW[128 * 3];
    __shared__ float sB[3];
    int tid = threadIdx.x;
    long m0 = (long)blockIdx.x * 32;
    for (int idx = tid; idx < 384; idx += 128) sW[idx] = __ldg(w + idx);
    if (tid < 3) sB[tid] = __ldg(bias + tid);
    for (int idx = tid; idx < 1024; idx += 128)
        ((float4*)sX)[idx] = __ldg((const float4*)(x + m0 * 128) + idx);
    __syncthreads();
    if (tid < 96) {
        int r = tid / 3, c = tid % 3;
        float a = sB[c];
        #pragma unroll 8
        for (int k = 0; k < 128; k++) a += sX[r * 128 + k] * sW[k * 3 + c];
        out[(m0 + r) * 3 + c] = a;
    }
}

// ===========================================================================
// spectral forward (FFMA outer-product reduction)
// ===========================================================================
#define SF_TS 16
__global__ __launch_bounds__(256) void spec_fwd_k(
    const float* __restrict__ evecs, const float* __restrict__ x,
    const float* __restrict__ mass, float* __restrict__ spec, int chunk)
{
    __shared__ float sE[SF_TS][128];
    __shared__ float sX[SF_TS][128];
    int b  = blockIdx.y;
    int n0 = blockIdx.x * chunk;
    int n1 = min(n0 + chunk, N_);
    int tid = threadIdx.x;
    int cg = tid & 15, kg = tid >> 4;
    int k0 = kg * 8, c0 = cg * 8;
    float acc[8][8];
    #pragma unroll
    for (int i = 0; i < 8; i++)
        #pragma unroll
        for (int j = 0; j < 8; j++) acc[i][j] = 0.f;

    const float* Eb = evecs + (long)b * N_ * 128;
    const float* Xb = x     + (long)b * N_ * 128;
    const float* Mb = mass  + (long)b * N_;

    for (int nt = n0; nt < n1; nt += SF_TS) {
        for (int idx = tid; idx < SF_TS * 32; idx += 256) {
            int r = idx >> 5, q = idx & 31;
            int n = nt + r;
            float4 e4 = make_float4(0.f, 0.f, 0.f, 0.f);
            float4 x4 = make_float4(0.f, 0.f, 0.f, 0.f);
            if (n < n1) {
                e4 = __ldg((const float4*)(Eb + (long)n * 128) + q);
                float m = __ldg(Mb + n);
                x4 = __ldg((const float4*)(Xb + (long)n * 128) + q);
                x4.x *= m; x4.y *= m; x4.z *= m; x4.w *= m;
            }
            ((float4*)sE[r])[q] = e4;
            ((float4*)sX[r])[q] = x4;
        }
        __syncthreads();
        #pragma unroll 4
        for (int t = 0; t < SF_TS; t++) {
            float4 ea = *(const float4*)&sE[t][k0];
            float4 eb = *(const float4*)&sE[t][k0 + 4];
            float4 xa = *(const float4*)&sX[t][c0];
            float4 xb = *(const float4*)&sX[t][c0 + 4];
            float e[8] = {ea.x, ea.y, ea.z, ea.w, eb.x, eb.y, eb.z, eb.w};
            float v[8] = {xa.x, xa.y, xa.z, xa.w, xb.x, xb.y, xb.z, xb.w};
            #pragma unroll
            for (int i = 0; i < 8; i++)
                #pragma unroll
                for (int j = 0; j < 8; j++) acc[i][j] += e[i] * v[j];
        }
        __syncthreads();
    }
    float* Sb = spec + (long)b * 128 * 128;
    #pragma unroll
    for (int i = 0; i < 8; i++)
        #pragma unroll
        for (int j = 0; j < 8; j++)
            atomicAdd(Sb + (long)(k0 + i) * 128 + (c0 + j), acc[i][j]);
}

// ===========================================================================
// W-image prep: transposed (Wt[n][k]), hi/lo split, padded row (136 k) bf16.
// ===========================================================================
__global__ __launch_bounds__(256) void prep_spec_k(
    const float* __restrict__ spec, const float* __restrict__ evals,
    const float* __restrict__ dt, unsigned* __restrict__ wimg)
{
    int b = blockIdx.x;
    const float* W  = spec  + (long)b * 16384;   // [k][c]
    const float* ev = evals + b * 128;
    unsigned* hi = wimg + (long)b * SLOT_U32;
    unsigned* lo = hi + IMG_U32;
    int tid = threadIdx.x;
    for (int idx = tid; idx < 8192; idx += 256) {
        int n = idx >> 6, kp = idx & 63;
        int k = kp * 2;
        float d = __ldg(dt + n);
        float v0 = __ldg(W + (k + 0) * 128 + n) * expf(-__ldg(ev + k + 0) * d);
        float v1 = __ldg(W + (k + 1) * 128 + n) * expf(-__ldg(ev + k + 1) * d);
        unsigned h, l;
        split2(v0, v1, h, l);
        hi[n * 68 + kp] = h;
        lo[n * 68 + kp] = l;
    }
}

__global__ __launch_bounds__(256) void prep_w_k(
    const float* __restrict__ W0, float s0, const float* __restrict__ W1, float s1,
    const float* __restrict__ W2, float s2, const float* __restrict__ W3, float s3,
    unsigned* __restrict__ wimg)
{
    int slot = blockIdx.x;
    const float* W = (slot == 0) ? W0 : (slot == 1) ? W1 : (slot == 2) ? W2 : W3;
    float s = (slot == 0) ? s0 : (slot == 1) ? s1 : (slot == 2) ? s2 : s3;
    unsigned* hi = wimg + (long)slot * SLOT_U32;
    unsigned* lo = hi + IMG_U32;
    int tid = threadIdx.x;
    for (int idx = tid; idx < 8192; idx += 256) {
        int n = idx >> 6, kp = idx & 63;
        int k = kp * 2;
        float v0 = __ldg(W + (k + 0) * 128 + n) * s;
        float v1 = __ldg(W + (k + 1) * 128 + n) * s;
        unsigned h, l;
        split2(v0, v1, h, l);
        hi[n * 68 + kp] = h;
        lo[n * 68 + kp] = l;
    }
}

// ===========================================================================
// mma.sync bf16x3 GEMM (cp.async W copies overlapping the A split)
// ===========================================================================
template <int ND>
__global__ __launch_bounds__(256, 1) void gemm_mma(
    const float* __restrict__ A0, const float* __restrict__ A1,
    const float* __restrict__ A2, const unsigned* __restrict__ wimg,
    int M, int num_in, int pbs, int epi,
    const float* __restrict__ bias, const float* __restrict__ resid,
    const float* __restrict__ gXp, const float* __restrict__ gYp,
    float* __restrict__ C)
{
    extern __shared__ char sb[];
    unsigned sbase = smem_u32(sb);

    int tid = threadIdx.x, wid = tid >> 5, lid = tid & 31;
    int zb = blockIdx.y;
    long aoff = (long)zb * M * 128;
    int m0 = blockIdx.x * 128;

    float acc[ND][2][8][4];
    #pragma unroll
    for (int d = 0; d < ND; d++)
        #pragma unroll
        for (int mt = 0; mt < 2; mt++)
            #pragma unroll
            for (int nt = 0; nt < 8; nt++)
                #pragma unroll
                for (int j = 0; j < 4; j++) acc[d][mt][nt][j] = 0.f;

    const float* As[3] = {A0, A1, A2};

    int q = lid >> 3, r = lid & 7;
    int mwarp = wid >> 1, nwarp = wid & 1;
    int a_row_in = (q & 1) * 8 + r;
    int a_koff   = (q >> 1) * 8;
    int b_row_in = (q >> 1) * 8 + r;
    int b_koff   = (q & 1) * 8;

    unsigned sA  = sbase;
    unsigned sAl = sbase + 34816u;
    unsigned sW0 = sbase + 2u * 34816u;

    unsigned aoffb[2], boffb[4];
    #pragma unroll
    for (int mt = 0; mt < 2; mt++)
        aoffb[mt] = (unsigned)((mwarp * 32 + mt * 16 + a_row_in) * 272 + a_koff * 2);
    #pragma unroll
    for (int np = 0; np < 4; np++)
        boffb[np] = (unsigned)((nwarp * 64 + np * 16 + b_row_in) * 272 + b_koff * 2);

    for (int jin = 0; jin < num_in; jin++) {
        __syncthreads();
        // async-copy ND W slots (hi+lo contiguous per slot)
        #pragma unroll
        for (int d = 0; d < ND; d++) {
            int slot = zb * pbs + jin * ND + d;
            const uint4* src = (const uint4*)(wimg + (long)slot * SLOT_U32);
            unsigned dst = sW0 + d * 69632u;
            #pragma unroll 4
            for (int idx = tid; idx < 4352; idx += 256)
                cp16(dst + idx * 16u, src + idx);
        }
        CP_COMMIT();
        // load + split A tile (overlaps with the async W copies)
        const float* A = As[jin] + aoff;
        #pragma unroll 4
        for (int idx = tid; idx < 4096; idx += 256) {
            int rr = idx >> 5, qq = idx & 31;
            int grow = m0 + rr;
            float4 v = make_float4(0.f, 0.f, 0.f, 0.f);
            if (grow < M) v = __ldg((const float4*)(A + (long)grow * 128) + qq);
            unsigned h0, l0, h1, l1;
            split2(v.x, v.y, h0, l0);
            split2(v.z, v.w, h1, l1);
            unsigned off = rr * 272 + qq * 8;
            *(uint2*)(sb + off)         = make_uint2(h0, h1);
            *(uint2*)(sb + 34816 + off) = make_uint2(l0, l1);
        }
        CP_WAIT0();
        __syncthreads();

        #pragma unroll
        for (int ks = 0; ks < 8; ks++) {
            unsigned kb = ks * 32;
            unsigned ah[2][4], al[2][4];
            #pragma unroll
            for (int mt = 0; mt < 2; mt++) {
                ldsm4(ah[mt], sA  + aoffb[mt] + kb);
                ldsm4(al[mt], sAl + aoffb[mt] + kb);
            }
            #pragma unroll
            for (int d = 0; d < ND; d++) {
                unsigned wHi = sW0 + d * 69632u;
                unsigned wLo = wHi + 34816u;
                #pragma unroll
                for (int np = 0; np < 4; np++) {
                    unsigned bh[4], bl[4];
                    ldsm4(bh, wHi + boffb[np] + kb);
                    ldsm4(bl, wLo + boffb[np] + kb);
                    #pragma unroll
                    for (int mt = 0; mt < 2; mt++) {
                        float* c0 = acc[d][mt][np * 2];
                        float* c1 = acc[d][mt][np * 2 + 1];
                        mma_bf16(c0, ah[mt], bh[0], bh[1]);
                        mma_bf16(c0, al[mt], bh[0], bh[1]);
                        mma_bf16(c0, ah[mt], bl[0], bl[1]);
                        mma_bf16(c1, ah[mt], bh[2], bh[3]);
                        mma_bf16(c1, al[mt], bh[2], bh[3]);
                        mma_bf16(c1, ah[mt], bl[2], bl[3]);
                    }
                }
            }
        }
    }

    // epilogue
    int colg = (lid & 3) * 2;
    int rowg = lid >> 2;
    #pragma unroll
    for (int mt = 0; mt < 2; mt++) {
        #pragma unroll
        for (int h = 0; h < 2; h++) {
            int row = m0 + mwarp * 32 + mt * 16 + rowg + h * 8;
            if (row >= M) continue;
            long rbase = aoff + (long)row * 128;
            #pragma unroll
            for (int nt = 0; nt < 8; nt++) {
                int col = nwarp * 64 + nt * 8 + colg;
                float v0 = acc[0][mt][nt][h * 2];
                float v1 = acc[0][mt][nt][h * 2 + 1];
                float o0, o1;
                if (epi == EPI2_GRAD) {
                    float w0 = acc[1][mt][nt][h * 2];
                    float w1 = acc[1][mt][nt][h * 2 + 1];
                    float2 gx = __ldg((const float2*)(gXp + rbase + col));
                    float2 gy = __ldg((const float2*)(gYp + rbase + col));
                    o0 = tanhf(gx.x * v0 + gy.x * w0);
                    o1 = tanhf(gx.y * v1 + gy.y * w1);
                } else if (epi == EPI2_NONE) {
                    o0 = v0; o1 = v1;
                } else {
                    float2 bv = __ldg((const float2*)(bias + col));
                    o0 = v0 + bv.x; o1 = v1 + bv.y;
                    if (epi == EPI2_RELU) {
                        o0 = fmaxf(o0, 0.f); o1 = fmaxf(o1, 0.f);
                    } else {   // EPI2_RES
                        float2 rv = __ldg((const float2*)(resid + rbase + col));
                        o0 += rv.x; o1 += rv.y;
                    }
                }
                *(float2*)(C + rbase + col) = make_float2(o0, o1);
            }
        }
    }
}

// ===========================================================================
extern "C" void kernel_launch(void* const* d_in, const int* in_sizes, int n_in,
                              void* d_out, int out_size)
{
    const float* x_in    = (const float*)d_in[0];
    const float* mass    = (const float*)d_in[1];
    const float* evals   = (const float*)d_in[2];
    const float* evecs   = (const float*)d_in[3];
    const int*   rows    = (const int*)  d_in[4];
    const int*   cols    = (const int*)  d_in[5];
    const float* gradX   = (const float*)d_in[6];
    const float* gradY   = (const float*)d_in[7];
    const float* w_first = (const float*)d_in[8];
    const float* b_first = (const float*)d_in[9];
    const float* dtim    = (const float*)d_in[10];
    const float* A_re    = (const float*)d_in[11];
    const float* A_im    = (const float*)d_in[12];
    const float* mlp_w0  = (const float*)d_in[13];
    const float* mlp_b0  = (const float*)d_in[14];
    const float* mlp_w1  = (const float*)d_in[15];
    const float* mlp_b1  = (const float*)d_in[16];
    const float* mlp_w2  = (const float*)d_in[17];
    const float* mlp_b2  = (const float*)d_in[18];
    const float* w_last  = (const float*)d_in[19];
    const float* b_last  = (const float*)d_in[20];
    float* out = (float*)d_out;

    float *x, *xd, *gX, *gY, *gf, *h1, *h2, *spec;
    unsigned* wimg;
    int *rowptr, *cursor, *perm;
    cudaGetSymbolAddress((void**)&x,     g_x);
    cudaGetSymbolAddress((void**)&xd,    g_xd);
    cudaGetSymbolAddress((void**)&gX,    g_gX);
    cudaGetSymbolAddress((void**)&gY,    g_gY);
    cudaGetSymbolAddress((void**)&gf,    g_gf);
    cudaGetSymbolAddress((void**)&h1,    g_h1);
    cudaGetSymbolAddress((void**)&h2,    g_h2);
    cudaGetSymbolAddress((void**)&spec,  g_spec);
    cudaGetSymbolAddress((void**)&wimg,  g_wimg);
    cudaGetSymbolAddress((void**)&rowptr, g_rowptr);
    cudaGetSymbolAddress((void**)&cursor, g_cursor);
    cudaGetSymbolAddress((void**)&perm,   g_perm);

    const int SMEM1 = 2 * 34816 + 1 * 69632;   // 139,264
    const int SMEM2 = 2 * 34816 + 2 * 69632;   // 208,896
    cudaFuncSetAttribute(gemm_mma<1>, cudaFuncAttributeMaxDynamicSharedMemorySize, SMEM1);
    cudaFuncSetAttribute(gemm_mma<2>, cudaFuncAttributeMaxDynamicSharedMemorySize, SMEM2);

    const float* nullf = nullptr;

    // ---- CSR build (once per launch; rows/cols shared across batches/iters) ----
    zero_i<<<(N_ + 1 + 255) / 256, 256>>>(rowptr, N_ + 1);
    hist_k<<<(E_ + 255) / 256, 256>>>(rows, rowptr);
    scan_k<<<1, 1024>>>(rowptr);
    cursor_k<<<(N_ + 255) / 256, 256>>>(rowptr, cursor);
    perm_k<<<(E_ + 255) / 256, 256>>>(rows, cursor, perm);

    first_k<<<ROWS_TOT / 32, 128>>>(x_in, w_first, b_first, x);

    for (int i = 0; i < 4; i++) {
        // --- spectral diffusion ---
        zero_k<<<64, 256>>>((float4*)spec, B_ * 128 * 128 / 4);
        spec_fwd_k<<<dim3((N_ + 511) / 512, B_), 256>>>(evecs, x, mass, spec, 512);
        prep_spec_k<<<4, 256>>>(spec, evals, dtim + i * CW_, wimg);
        gemm_mma<1><<<dim3((N_ + 127) / 128, B_), 256, SMEM1>>>(
            evecs, nullf, nullf, wimg, N_, 1, 1, EPI2_NONE,
            nullf, nullf, nullf, nullf, xd);

        // --- sparse gradients (CSR gather, no atomics) ---
        spmm_gather_k<<<dim3(N_ / SG_ROWS, B_), 128>>>(
            rowptr, perm, cols, gradX, gradY, xd, gX, gY);

        // --- rotation + tanh gradient features (fused, dual accumulators) ---
        const float* Are = A_re + (long)i * CW_ * CW_;
        const float* Aim = A_im + (long)i * CW_ * CW_;
        prep_w_k<<<4, 256>>>(Are, 1.f, Aim, 1.f, Aim, -1.f, Are, 1.f, wimg);
        gemm_mma<2><<<dim3(ROWS_TOT / 128, 1), 256, SMEM2>>>(
            gX, gY, nullf, wimg, ROWS_TOT, 2, 4, EPI2_GRAD,
            nullf, nullf, gX, gY, gf);

        // --- MiniMLP + residual ---
        const float* W0 = mlp_w0 + (long)i * 3 * CW_ * CW_;
        prep_w_k<<<3, 256>>>(W0, 1.f, W0 + 16384, 1.f, W0 + 32768, 1.f, nullf, 0.f, wimg);
        gemm_mma<1><<<dim3(ROWS_TOT / 128, 1), 256, SMEM1>>>(
            x, xd, gf, wimg, ROWS_TOT, 3, 3, EPI2_RELU,
            mlp_b0 + i * CW_, nullf, nullf, nullf, h1);

        prep_w_k<<<1, 256>>>(mlp_w1 + (long)i * CW_ * CW_, 1.f, nullf, 0.f,
                             nullf, 0.f, nullf, 0.f, wimg);
        gemm_mma<1><<<dim3(ROWS_TOT / 128, 1), 256, SMEM1>>>(
            h1, nullf, nullf, wimg, ROWS_TOT, 1, 1, EPI2_RELU,
            mlp_b1 + i * CW_, nullf, nullf, nullf, h2);

        prep_w_k<<<1, 256>>>(mlp_w2 + (long)i * CW_ * CW_, 1.f, nullf, 0.f,
                             nullf, 0.f, nullf, 0.f, wimg);
        gemm_mma<1><<<dim3(ROWS_TOT / 128, 1), 256, SMEM1>>>(
            h2, nullf, nullf, wimg, ROWS_TOT, 1, 1, EPI2_RES,
            mlp_b2 + i * CW_, x, nullf, nullf, x);
    }

    last_k<<<ROWS_TOT / 32, 128>>>(x, w_last, b_last, out);
}